// round 11
// baseline (speedup 1.0000x reference)
#include <cuda_runtime.h>
#include <cuda_bf16.h>
#include <cstdint>

// Problem constants
#define NXg 512
#define NYg 512
#define NSENS 128
#define NT 2048
#define NPIX (NXg * NYg)

// Two half-channel scratch arrays: [s][t][4ch] as one float4 per (s,t).
__device__ float4 g_scratchA[NSENS * NT];   // channels 0..3
__device__ float4 g_scratchB[NSENS * NT];   // channels 4..7

// ---------------------------------------------------------------------------
// Prep kernel: transpose sensor_data [B=4][C=2][S=128][T=2048] -> 2x [S][T][4]
// Each thread handles 4 consecutive t: 8x LDG.128 in, 8x STG.128 out.
// ---------------------------------------------------------------------------
__global__ __launch_bounds__(256) void das_transpose_kernel(
    const float* __restrict__ sd)
{
    int idx = blockIdx.x * blockDim.x + threadIdx.x;   // 0 .. 128*512-1
    if (idx >= NSENS * (NT / 4)) return;
    int s  = idx >> 9;                 // sensor
    int tq = (idx & 511) << 2;         // t base (multiple of 4)

    const int bcStride = NSENS * NT;   // 262144 floats per (b,c) plane
    const float* base = sd + s * NT + tq;

    float4 c0 = *(const float4*)(base + 0 * bcStride);
    float4 c1 = *(const float4*)(base + 1 * bcStride);
    float4 c2 = *(const float4*)(base + 2 * bcStride);
    float4 c3 = *(const float4*)(base + 3 * bcStride);
    float4 c4 = *(const float4*)(base + 4 * bcStride);
    float4 c5 = *(const float4*)(base + 5 * bcStride);
    float4 c6 = *(const float4*)(base + 6 * bcStride);
    float4 c7 = *(const float4*)(base + 7 * bcStride);

    unsigned e = ((unsigned)s << 11) + (unsigned)tq;
    g_scratchA[e + 0] = make_float4(c0.x, c1.x, c2.x, c3.x);
    g_scratchA[e + 1] = make_float4(c0.y, c1.y, c2.y, c3.y);
    g_scratchA[e + 2] = make_float4(c0.z, c1.z, c2.z, c3.z);
    g_scratchA[e + 3] = make_float4(c0.w, c1.w, c2.w, c3.w);
    g_scratchB[e + 0] = make_float4(c4.x, c5.x, c6.x, c7.x);
    g_scratchB[e + 1] = make_float4(c4.y, c5.y, c6.y, c7.y);
    g_scratchB[e + 2] = make_float4(c4.z, c5.z, c6.z, c7.z);
    g_scratchB[e + 3] = make_float4(c4.w, c5.w, c6.w, c7.w);
}

// ---------------------------------------------------------------------------
// Main DAS kernel. Warp patch 8(iy) x 4(ix) => per-sensor t-span <= 21 < 32.
// Gather strategy: warp-min of t, COALESCED load of the 32-entry window
// (lane l loads entry tmin+l), then per-pixel values picked via SHFL.IDX.
// Converts scattered 2.07-cyc/wf L1 returns into coalesced 1.0-cyc/wf ones.
// ---------------------------------------------------------------------------
__global__ __launch_bounds__(128) void das_main_kernel(
    const int* __restrict__ sensor_xy,   // [128][2] int32
    float* __restrict__ out)             // [8][NPIX]
{
    __shared__ float2 sxy[NSENS];

    const int tid  = threadIdx.x;        // 0..127
    const int lane = tid & 31;
    const int w    = tid >> 5;           // 0..3

    {
        int2 xy = ((const int2*)sensor_xy)[tid];
        sxy[tid] = make_float2((float)xy.x, (float)xy.y);
    }
    __syncthreads();

    // Warp patch: 8 iy x 4 ix. Warps tile 2(iy) x 2(ix) over a 16x8 tile.
    const int ly = lane & 7;
    const int lx = lane >> 3;
    const int wy = w & 1;
    const int wx = w >> 1;

    const int iy = blockIdx.x * 16 + wy * 8 + ly;
    const int ix = blockIdx.y * 8 + wx * 4 + lx;

    const float fix = (float)ix;
    const float fiy = (float)iy;

    // XLA chain (bit-exact, validated R3): dis * fl(fl(1/VS)*fl(1/DT)).
    const float K = (1.0f / 1550.0f) * (1.0f / 2.5e-8f);

    float4 a0 = make_float4(0.f, 0.f, 0.f, 0.f);
    float4 a1 = make_float4(0.f, 0.f, 0.f, 0.f);

    #pragma unroll 4
    for (int s = 0; s < NSENS; ++s) {
        float2 c = sxy[s];
        float dx = __fmul_rn(c.x - fix, 1e-4f);
        float dy = __fmul_rn(c.y - fiy, 1e-4f);
        float r2 = __fadd_rn(__fmul_rn(dx, dx), __fmul_rn(dy, dy));
        float dis = __fsqrt_rn(r2);
        int t = (int)__fmul_rn(dis, K);

        // Warp window base: span(t) <= 21 < 32, so [tmin, tmin+31] covers all.
        int tmin = __reduce_min_sync(0xffffffffu, t);
        int src  = t - tmin;                          // 0..21

        unsigned off = ((unsigned)s << 11) + (unsigned)(tmin + lane);
        float4 va = __ldg(&g_scratchA[off]);          // coalesced 512B
        float4 vb = __ldg(&g_scratchB[off]);          // coalesced 512B

        a0.x += __shfl_sync(0xffffffffu, va.x, src);
        a0.y += __shfl_sync(0xffffffffu, va.y, src);
        a0.z += __shfl_sync(0xffffffffu, va.z, src);
        a0.w += __shfl_sync(0xffffffffu, va.w, src);
        a1.x += __shfl_sync(0xffffffffu, vb.x, src);
        a1.y += __shfl_sync(0xffffffffu, vb.y, src);
        a1.z += __shfl_sync(0xffffffffu, vb.z, src);
        a1.w += __shfl_sync(0xffffffffu, vb.w, src);
    }

    const int p = ix * NYg + iy;
    out[0 * NPIX + p] = a0.x;
    out[1 * NPIX + p] = a0.y;
    out[2 * NPIX + p] = a0.z;
    out[3 * NPIX + p] = a0.w;
    out[4 * NPIX + p] = a1.x;
    out[5 * NPIX + p] = a1.y;
    out[6 * NPIX + p] = a1.z;
    out[7 * NPIX + p] = a1.w;
}

// ---------------------------------------------------------------------------
// Entry point
// ---------------------------------------------------------------------------
extern "C" void kernel_launch(void* const* d_in, const int* in_sizes, int n_in,
                              void* d_out, int out_size)
{
    const float* sensor_data = (const float*)d_in[0];   // (4,2,128,2048) f32
    const int*   sensor_xy   = (const int*)d_in[1];     // (128,2) i32
    float*       out         = (float*)d_out;           // (4,2,512,512) f32

    das_transpose_kernel<<<(NSENS * (NT / 4) + 255) / 256, 256>>>(sensor_data);

    dim3 block(128);
    dim3 grid(NYg / 16, NXg / 8);
    das_main_kernel<<<grid, block>>>(sensor_xy, out);
}

// round 12
// speedup vs baseline: 1.3692x; 1.3692x over previous
#include <cuda_runtime.h>
#include <cuda_bf16.h>
#include <cstdint>

// Problem constants
#define NXg 512
#define NYg 512
#define NSENS 128
#define NT 2048
#define NPIX (NXg * NYg)

// Two half-channel scratch arrays: [s][t][4ch] as one float4 per (s,t).
// 4 MB each; a 128B line holds 8 consecutive t entries -> low line overfetch.
__device__ float4 g_scratchA[NSENS * NT];   // channels 0..3
__device__ float4 g_scratchB[NSENS * NT];   // channels 4..7

// ---------------------------------------------------------------------------
// Prep kernel: transpose sensor_data [B=4][C=2][S=128][T=2048] -> 2x [S][T][4]
// Each thread handles 4 consecutive t: 8x LDG.128 in, register 4x4 transpose,
// 8x STG.128 out. Fully coalesced both sides. (R11-measured: ~4.3us overhead.)
// ---------------------------------------------------------------------------
__global__ __launch_bounds__(256) void das_transpose_kernel(
    const float* __restrict__ sd)
{
    int idx = blockIdx.x * blockDim.x + threadIdx.x;   // 0 .. 128*512-1
    if (idx >= NSENS * (NT / 4)) return;
    int s  = idx >> 9;                 // sensor
    int tq = (idx & 511) << 2;         // t base (multiple of 4)

    const int bcStride = NSENS * NT;   // 262144 floats per (b,c) plane
    const float* base = sd + s * NT + tq;

    float4 c0 = *(const float4*)(base + 0 * bcStride);
    float4 c1 = *(const float4*)(base + 1 * bcStride);
    float4 c2 = *(const float4*)(base + 2 * bcStride);
    float4 c3 = *(const float4*)(base + 3 * bcStride);
    float4 c4 = *(const float4*)(base + 4 * bcStride);
    float4 c5 = *(const float4*)(base + 5 * bcStride);
    float4 c6 = *(const float4*)(base + 6 * bcStride);
    float4 c7 = *(const float4*)(base + 7 * bcStride);

    unsigned e = ((unsigned)s << 11) + (unsigned)tq;
    g_scratchA[e + 0] = make_float4(c0.x, c1.x, c2.x, c3.x);
    g_scratchA[e + 1] = make_float4(c0.y, c1.y, c2.y, c3.y);
    g_scratchA[e + 2] = make_float4(c0.z, c1.z, c2.z, c3.z);
    g_scratchA[e + 3] = make_float4(c0.w, c1.w, c2.w, c3.w);
    g_scratchB[e + 0] = make_float4(c4.x, c5.x, c6.x, c7.x);
    g_scratchB[e + 1] = make_float4(c4.y, c5.y, c6.y, c7.y);
    g_scratchB[e + 2] = make_float4(c4.z, c5.z, c6.z, c7.z);
    g_scratchB[e + 3] = make_float4(c4.w, c5.w, c6.w, c7.w);
}

// ---------------------------------------------------------------------------
// Main DAS kernel (R10 — best measured: 64.4us).
// One thread per pixel, 128-sensor loop. 128-thread blocks (4 warps,
// 16iy x 8ix tile) minimize wave-tail imbalance; warp patch 8(iy) x 4(ix)
// is the validated minimum-delay-span geometry. Direct scattered LDG.128
// pair per sensor — measured at the L1 scattered-return floor.
// ---------------------------------------------------------------------------
__global__ __launch_bounds__(128) void das_main_kernel(
    const int* __restrict__ sensor_xy,   // [128][2] int32
    float* __restrict__ out)             // [8][NPIX]
{
    __shared__ float2 sxy[NSENS];

    const int tid  = threadIdx.x;        // 0..127
    const int lane = tid & 31;
    const int w    = tid >> 5;           // 0..3

    {
        int2 xy = ((const int2*)sensor_xy)[tid];
        sxy[tid] = make_float2((float)xy.x, (float)xy.y);
    }
    __syncthreads();

    // Warp patch: 8 iy x 4 ix. Warps tile 2(iy) x 2(ix) over a 16x8 tile.
    const int ly = lane & 7;
    const int lx = lane >> 3;
    const int wy = w & 1;
    const int wx = w >> 1;

    const int iy = blockIdx.x * 16 + wy * 8 + ly;
    const int ix = blockIdx.y * 8 + wx * 4 + lx;

    const float fix = (float)ix;
    const float fiy = (float)iy;

    // XLA chain (bit-exact, validated R3): dis * fl(fl(1/VS)*fl(1/DT)).
    const float K = (1.0f / 1550.0f) * (1.0f / 2.5e-8f);

    float4 a0 = make_float4(0.f, 0.f, 0.f, 0.f);
    float4 a1 = make_float4(0.f, 0.f, 0.f, 0.f);

    #pragma unroll 4
    for (int s = 0; s < NSENS; ++s) {
        float2 c = sxy[s];
        float dx = __fmul_rn(c.x - fix, 1e-4f);
        float dy = __fmul_rn(c.y - fiy, 1e-4f);
        float r2 = __fadd_rn(__fmul_rn(dx, dx), __fmul_rn(dy, dy));
        float dis = __fsqrt_rn(r2);
        int t = (int)__fmul_rn(dis, K);

        unsigned off = ((unsigned)s << 11) + (unsigned)t;
        float4 v0 = __ldg(&g_scratchA[off]);
        float4 v1 = __ldg(&g_scratchB[off]);
        a0.x += v0.x; a0.y += v0.y; a0.z += v0.z; a0.w += v0.w;
        a1.x += v1.x; a1.y += v1.y; a1.z += v1.z; a1.w += v1.w;
    }

    const int p = ix * NYg + iy;
    out[0 * NPIX + p] = a0.x;
    out[1 * NPIX + p] = a0.y;
    out[2 * NPIX + p] = a0.z;
    out[3 * NPIX + p] = a0.w;
    out[4 * NPIX + p] = a1.x;
    out[5 * NPIX + p] = a1.y;
    out[6 * NPIX + p] = a1.z;
    out[7 * NPIX + p] = a1.w;
}

// ---------------------------------------------------------------------------
// Entry point
// ---------------------------------------------------------------------------
extern "C" void kernel_launch(void* const* d_in, const int* in_sizes, int n_in,
                              void* d_out, int out_size)
{
    const float* sensor_data = (const float*)d_in[0];   // (4,2,128,2048) f32
    const int*   sensor_xy   = (const int*)d_in[1];     // (128,2) i32
    float*       out         = (float*)d_out;           // (4,2,512,512) f32

    das_transpose_kernel<<<(NSENS * (NT / 4) + 255) / 256, 256>>>(sensor_data);

    dim3 block(128);
    dim3 grid(NYg / 16, NXg / 8);
    das_main_kernel<<<grid, block>>>(sensor_xy, out);
}

// round 13
// speedup vs baseline: 1.5198x; 1.1099x over previous
#include <cuda_runtime.h>
#include <cuda_bf16.h>
#include <cuda_fp16.h>
#include <cstdint>

// Problem constants
#define NXg 512
#define NYg 512
#define NSENS 128
#define NT 2048
#define NPIX (NXg * NYg)

// fp16 scratch: [s][t] -> 8 channels x half = 16B entry. 4 MB total.
// One LDG.128 fetches ALL 8 channels for a (pixel,sensor) pair.
__device__ uint4 g_scratchH[NSENS * NT];

__device__ __forceinline__ unsigned pack2(float a, float b) {
    __half2 h = __floats2half2_rn(a, b);
    return *(unsigned*)&h;
}

// ---------------------------------------------------------------------------
// Prep kernel: transpose+quantize sensor_data [B=4][C=2][S=128][T=2048]
// -> [S][T][8ch fp16]. Each thread handles 4 consecutive t.
// ---------------------------------------------------------------------------
__global__ __launch_bounds__(256) void das_transpose_kernel(
    const float* __restrict__ sd)
{
    int idx = blockIdx.x * blockDim.x + threadIdx.x;   // 0 .. 128*512-1
    if (idx >= NSENS * (NT / 4)) return;
    int s  = idx >> 9;                 // sensor
    int tq = (idx & 511) << 2;         // t base (multiple of 4)

    const int bcStride = NSENS * NT;   // 262144 floats per (b,c) plane
    const float* base = sd + s * NT + tq;

    float4 c0 = *(const float4*)(base + 0 * bcStride);
    float4 c1 = *(const float4*)(base + 1 * bcStride);
    float4 c2 = *(const float4*)(base + 2 * bcStride);
    float4 c3 = *(const float4*)(base + 3 * bcStride);
    float4 c4 = *(const float4*)(base + 4 * bcStride);
    float4 c5 = *(const float4*)(base + 5 * bcStride);
    float4 c6 = *(const float4*)(base + 6 * bcStride);
    float4 c7 = *(const float4*)(base + 7 * bcStride);

    unsigned e = ((unsigned)s << 11) + (unsigned)tq;

    g_scratchH[e + 0] = make_uint4(pack2(c0.x, c1.x), pack2(c2.x, c3.x),
                                   pack2(c4.x, c5.x), pack2(c6.x, c7.x));
    g_scratchH[e + 1] = make_uint4(pack2(c0.y, c1.y), pack2(c2.y, c3.y),
                                   pack2(c4.y, c5.y), pack2(c6.y, c7.y));
    g_scratchH[e + 2] = make_uint4(pack2(c0.z, c1.z), pack2(c2.z, c3.z),
                                   pack2(c4.z, c5.z), pack2(c6.z, c7.z));
    g_scratchH[e + 3] = make_uint4(pack2(c0.w, c1.w), pack2(c2.w, c3.w),
                                   pack2(c4.w, c5.w), pack2(c6.w, c7.w));
}

// ---------------------------------------------------------------------------
// Main DAS kernel. Geometry identical to R10/R12 (validated optimum):
// 128-thread blocks, 16iy x 8ix tile, warp patch 8(iy) x 4(ix).
// Gather: ONE LDG.128 per (pixel,sensor) = all 8 channels in fp16;
// convert to f32 and accumulate in f32 (quantization-only error ~2.5e-4).
// ---------------------------------------------------------------------------
__global__ __launch_bounds__(128) void das_main_kernel(
    const int* __restrict__ sensor_xy,   // [128][2] int32
    float* __restrict__ out)             // [8][NPIX]
{
    __shared__ float2 sxy[NSENS];

    const int tid  = threadIdx.x;        // 0..127
    const int lane = tid & 31;
    const int w    = tid >> 5;           // 0..3

    {
        int2 xy = ((const int2*)sensor_xy)[tid];
        sxy[tid] = make_float2((float)xy.x, (float)xy.y);
    }
    __syncthreads();

    const int ly = lane & 7;
    const int lx = lane >> 3;
    const int wy = w & 1;
    const int wx = w >> 1;

    const int iy = blockIdx.x * 16 + wy * 8 + ly;
    const int ix = blockIdx.y * 8 + wx * 4 + lx;

    const float fix = (float)ix;
    const float fiy = (float)iy;

    // XLA chain (bit-exact, validated R3): dis * fl(fl(1/VS)*fl(1/DT)).
    // Indices MUST remain bit-exact — only the gathered VALUES are fp16.
    const float K = (1.0f / 1550.0f) * (1.0f / 2.5e-8f);

    float a0 = 0.f, a1 = 0.f, a2 = 0.f, a3 = 0.f;
    float a4 = 0.f, a5 = 0.f, a6 = 0.f, a7 = 0.f;

    #pragma unroll 4
    for (int s = 0; s < NSENS; ++s) {
        float2 c = sxy[s];
        float dx = __fmul_rn(c.x - fix, 1e-4f);
        float dy = __fmul_rn(c.y - fiy, 1e-4f);
        float r2 = __fadd_rn(__fmul_rn(dx, dx), __fmul_rn(dy, dy));
        float dis = __fsqrt_rn(r2);
        int t = (int)__fmul_rn(dis, K);

        unsigned off = ((unsigned)s << 11) + (unsigned)t;
        uint4 v = __ldg(&g_scratchH[off]);

        float2 f01 = __half22float2(*(__half2*)&v.x);
        float2 f23 = __half22float2(*(__half2*)&v.y);
        float2 f45 = __half22float2(*(__half2*)&v.z);
        float2 f67 = __half22float2(*(__half2*)&v.w);

        a0 += f01.x; a1 += f01.y;
        a2 += f23.x; a3 += f23.y;
        a4 += f45.x; a5 += f45.y;
        a6 += f67.x; a7 += f67.y;
    }

    const int p = ix * NYg + iy;
    out[0 * NPIX + p] = a0;
    out[1 * NPIX + p] = a1;
    out[2 * NPIX + p] = a2;
    out[3 * NPIX + p] = a3;
    out[4 * NPIX + p] = a4;
    out[5 * NPIX + p] = a5;
    out[6 * NPIX + p] = a6;
    out[7 * NPIX + p] = a7;
}

// ---------------------------------------------------------------------------
// Entry point
// ---------------------------------------------------------------------------
extern "C" void kernel_launch(void* const* d_in, const int* in_sizes, int n_in,
                              void* d_out, int out_size)
{
    const float* sensor_data = (const float*)d_in[0];   // (4,2,128,2048) f32
    const int*   sensor_xy   = (const int*)d_in[1];     // (128,2) i32
    float*       out         = (float*)d_out;           // (4,2,512,512) f32

    das_transpose_kernel<<<(NSENS * (NT / 4) + 255) / 256, 256>>>(sensor_data);

    dim3 block(128);
    dim3 grid(NYg / 16, NXg / 8);
    das_main_kernel<<<grid, block>>>(sensor_xy, out);
}

// round 14
// speedup vs baseline: 1.7783x; 1.1701x over previous
#include <cuda_runtime.h>
#include <cuda_bf16.h>
#include <cuda_fp16.h>
#include <cstdint>

// Problem constants
#define NXg 512
#define NYg 512
#define NSENS 128
#define NT 2048
#define NPIX (NXg * NYg)

// fp16 scratch: [s][t] -> 8 channels x half = 16B entry. 4 MB total.
// One LDG.128 fetches ALL 8 channels for a (pixel,sensor) pair.
__device__ uint4 g_scratchH[NSENS * NT];

__device__ __forceinline__ unsigned pack2(float a, float b) {
    __half2 h = __floats2half2_rn(a, b);
    return *(unsigned*)&h;
}

// ---------------------------------------------------------------------------
// Prep kernel: transpose+quantize sensor_data [B=4][C=2][S=128][T=2048]
// -> [S][T][8ch fp16]. Each thread handles 4 consecutive t.
// ---------------------------------------------------------------------------
__global__ __launch_bounds__(256) void das_transpose_kernel(
    const float* __restrict__ sd)
{
    int idx = blockIdx.x * blockDim.x + threadIdx.x;   // 0 .. 128*512-1
    if (idx >= NSENS * (NT / 4)) return;
    int s  = idx >> 9;                 // sensor
    int tq = (idx & 511) << 2;         // t base (multiple of 4)

    const int bcStride = NSENS * NT;   // 262144 floats per (b,c) plane
    const float* base = sd + s * NT + tq;

    float4 c0 = *(const float4*)(base + 0 * bcStride);
    float4 c1 = *(const float4*)(base + 1 * bcStride);
    float4 c2 = *(const float4*)(base + 2 * bcStride);
    float4 c3 = *(const float4*)(base + 3 * bcStride);
    float4 c4 = *(const float4*)(base + 4 * bcStride);
    float4 c5 = *(const float4*)(base + 5 * bcStride);
    float4 c6 = *(const float4*)(base + 6 * bcStride);
    float4 c7 = *(const float4*)(base + 7 * bcStride);

    unsigned e = ((unsigned)s << 11) + (unsigned)tq;

    g_scratchH[e + 0] = make_uint4(pack2(c0.x, c1.x), pack2(c2.x, c3.x),
                                   pack2(c4.x, c5.x), pack2(c6.x, c7.x));
    g_scratchH[e + 1] = make_uint4(pack2(c0.y, c1.y), pack2(c2.y, c3.y),
                                   pack2(c4.y, c5.y), pack2(c6.y, c7.y));
    g_scratchH[e + 2] = make_uint4(pack2(c0.z, c1.z), pack2(c2.z, c3.z),
                                   pack2(c4.z, c5.z), pack2(c6.z, c7.z));
    g_scratchH[e + 3] = make_uint4(pack2(c0.w, c1.w), pack2(c2.w, c3.w),
                                   pack2(c4.w, c5.w), pack2(c6.w, c7.w));
}

// ---------------------------------------------------------------------------
// Main DAS kernel. Geometry identical to R10/R12/R13 (validated optimum):
// 128-thread blocks, 16iy x 8ix tile, warp patch 8(iy) x 4(ix).
// Sensors processed in PAIRS: gathered fp16 values of sensors s and s+1 are
// pre-added with HADD2 (one extra fp16 rounding, ~+2e-4 rel err), halving
// the F2F conversion count and the f32 accumulation count.
// ---------------------------------------------------------------------------
__global__ __launch_bounds__(128) void das_main_kernel(
    const int* __restrict__ sensor_xy,   // [128][2] int32
    float* __restrict__ out)             // [8][NPIX]
{
    __shared__ float2 sxy[NSENS];

    const int tid  = threadIdx.x;        // 0..127
    const int lane = tid & 31;
    const int w    = tid >> 5;           // 0..3

    {
        int2 xy = ((const int2*)sensor_xy)[tid];
        sxy[tid] = make_float2((float)xy.x, (float)xy.y);
    }
    __syncthreads();

    const int ly = lane & 7;
    const int lx = lane >> 3;
    const int wy = w & 1;
    const int wx = w >> 1;

    const int iy = blockIdx.x * 16 + wy * 8 + ly;
    const int ix = blockIdx.y * 8 + wx * 4 + lx;

    const float fix = (float)ix;
    const float fiy = (float)iy;

    // XLA chain (bit-exact, validated R3): dis * fl(fl(1/VS)*fl(1/DT)).
    // Indices MUST remain bit-exact — only the gathered VALUES are fp16.
    const float K = (1.0f / 1550.0f) * (1.0f / 2.5e-8f);

    float a0 = 0.f, a1 = 0.f, a2 = 0.f, a3 = 0.f;
    float a4 = 0.f, a5 = 0.f, a6 = 0.f, a7 = 0.f;

    #pragma unroll 4
    for (int s = 0; s < NSENS; s += 2) {
        // --- two independent index chains (bit-exact) ---
        float2 cA = sxy[s];
        float2 cB = sxy[s + 1];

        float dxA = __fmul_rn(cA.x - fix, 1e-4f);
        float dyA = __fmul_rn(cA.y - fiy, 1e-4f);
        float dxB = __fmul_rn(cB.x - fix, 1e-4f);
        float dyB = __fmul_rn(cB.y - fiy, 1e-4f);

        float rA = __fadd_rn(__fmul_rn(dxA, dxA), __fmul_rn(dyA, dyA));
        float rB = __fadd_rn(__fmul_rn(dxB, dxB), __fmul_rn(dyB, dyB));

        int tA = (int)__fmul_rn(__fsqrt_rn(rA), K);
        int tB = (int)__fmul_rn(__fsqrt_rn(rB), K);

        uint4 vA = __ldg(&g_scratchH[(((unsigned)s)       << 11) + (unsigned)tA]);
        uint4 vB = __ldg(&g_scratchH[(((unsigned)(s + 1)) << 11) + (unsigned)tB]);

        // --- pairwise fp16 pre-add, then convert+accumulate in f32 ---
        __half2 h0 = __hadd2(*(__half2*)&vA.x, *(__half2*)&vB.x);
        __half2 h1 = __hadd2(*(__half2*)&vA.y, *(__half2*)&vB.y);
        __half2 h2 = __hadd2(*(__half2*)&vA.z, *(__half2*)&vB.z);
        __half2 h3 = __hadd2(*(__half2*)&vA.w, *(__half2*)&vB.w);

        float2 f01 = __half22float2(h0);
        float2 f23 = __half22float2(h1);
        float2 f45 = __half22float2(h2);
        float2 f67 = __half22float2(h3);

        a0 += f01.x; a1 += f01.y;
        a2 += f23.x; a3 += f23.y;
        a4 += f45.x; a5 += f45.y;
        a6 += f67.x; a7 += f67.y;
    }

    const int p = ix * NYg + iy;
    out[0 * NPIX + p] = a0;
    out[1 * NPIX + p] = a1;
    out[2 * NPIX + p] = a2;
    out[3 * NPIX + p] = a3;
    out[4 * NPIX + p] = a4;
    out[5 * NPIX + p] = a5;
    out[6 * NPIX + p] = a6;
    out[7 * NPIX + p] = a7;
}

// ---------------------------------------------------------------------------
// Entry point
// ---------------------------------------------------------------------------
extern "C" void kernel_launch(void* const* d_in, const int* in_sizes, int n_in,
                              void* d_out, int out_size)
{
    const float* sensor_data = (const float*)d_in[0];   // (4,2,128,2048) f32
    const int*   sensor_xy   = (const int*)d_in[1];     // (128,2) i32
    float*       out         = (float*)d_out;           // (4,2,512,512) f32

    das_transpose_kernel<<<(NSENS * (NT / 4) + 255) / 256, 256>>>(sensor_data);

    dim3 block(128);
    dim3 grid(NYg / 16, NXg / 8);
    das_main_kernel<<<grid, block>>>(sensor_xy, out);
}

// round 15
// speedup vs baseline: 1.9789x; 1.1128x over previous
#include <cuda_runtime.h>
#include <cuda_bf16.h>
#include <cuda_fp16.h>
#include <cstdint>

// Problem constants
#define NXg 512
#define NYg 512
#define NSENS 128
#define NT 2048
#define NPIX (NXg * NYg)

// fp16 scratch: [s][t] -> 8 channels x half = 16B entry. 4 MB total.
// One LDG.128 fetches ALL 8 channels for a (pixel,sensor) pair.
__device__ uint4 g_scratchH[NSENS * NT];

__device__ __forceinline__ unsigned pack2(float a, float b) {
    __half2 h = __floats2half2_rn(a, b);
    return *(unsigned*)&h;
}
__device__ __forceinline__ __half2 h2(unsigned u) { return *(__half2*)&u; }

// ---------------------------------------------------------------------------
// Prep kernel: transpose+quantize sensor_data [B=4][C=2][S=128][T=2048]
// -> [S][T][8ch fp16]. Each thread handles 4 consecutive t.
// ---------------------------------------------------------------------------
__global__ __launch_bounds__(256) void das_transpose_kernel(
    const float* __restrict__ sd)
{
    int idx = blockIdx.x * blockDim.x + threadIdx.x;   // 0 .. 128*512-1
    if (idx >= NSENS * (NT / 4)) return;
    int s  = idx >> 9;                 // sensor
    int tq = (idx & 511) << 2;         // t base (multiple of 4)

    const int bcStride = NSENS * NT;   // 262144 floats per (b,c) plane
    const float* base = sd + s * NT + tq;

    float4 c0 = *(const float4*)(base + 0 * bcStride);
    float4 c1 = *(const float4*)(base + 1 * bcStride);
    float4 c2 = *(const float4*)(base + 2 * bcStride);
    float4 c3 = *(const float4*)(base + 3 * bcStride);
    float4 c4 = *(const float4*)(base + 4 * bcStride);
    float4 c5 = *(const float4*)(base + 5 * bcStride);
    float4 c6 = *(const float4*)(base + 6 * bcStride);
    float4 c7 = *(const float4*)(base + 7 * bcStride);

    unsigned e = ((unsigned)s << 11) + (unsigned)tq;

    g_scratchH[e + 0] = make_uint4(pack2(c0.x, c1.x), pack2(c2.x, c3.x),
                                   pack2(c4.x, c5.x), pack2(c6.x, c7.x));
    g_scratchH[e + 1] = make_uint4(pack2(c0.y, c1.y), pack2(c2.y, c3.y),
                                   pack2(c4.y, c5.y), pack2(c6.y, c7.y));
    g_scratchH[e + 2] = make_uint4(pack2(c0.z, c1.z), pack2(c2.z, c3.z),
                                   pack2(c4.z, c5.z), pack2(c6.z, c7.z));
    g_scratchH[e + 3] = make_uint4(pack2(c0.w, c1.w), pack2(c2.w, c3.w),
                                   pack2(c4.w, c5.w), pack2(c6.w, c7.w));
}

// ---------------------------------------------------------------------------
// Main DAS kernel. Geometry from R10 (validated optimum): 128-thread blocks,
// 16iy x 8ix tile, warp patch 8(iy) x 4(ix).
// Sensors processed in QUADS: fp16 values of 4 sensors reduced with a
// 2-level HADD2 tree before f32 conversion+accumulation. Index chains remain
// bit-exact per sensor (frozen since R3).
// ---------------------------------------------------------------------------
__global__ __launch_bounds__(128) void das_main_kernel(
    const int* __restrict__ sensor_xy,   // [128][2] int32
    float* __restrict__ out)             // [8][NPIX]
{
    __shared__ float2 sxy[NSENS];

    const int tid  = threadIdx.x;        // 0..127
    const int lane = tid & 31;
    const int w    = tid >> 5;           // 0..3

    {
        int2 xy = ((const int2*)sensor_xy)[tid];
        sxy[tid] = make_float2((float)xy.x, (float)xy.y);
    }
    __syncthreads();

    const int ly = lane & 7;
    const int lx = lane >> 3;
    const int wy = w & 1;
    const int wx = w >> 1;

    const int iy = blockIdx.x * 16 + wy * 8 + ly;
    const int ix = blockIdx.y * 8 + wx * 4 + lx;

    const float fix = (float)ix;
    const float fiy = (float)iy;

    // XLA chain (bit-exact, validated R3): dis * fl(fl(1/VS)*fl(1/DT)).
    // Indices MUST remain bit-exact — only the gathered VALUES are fp16.
    const float K = (1.0f / 1550.0f) * (1.0f / 2.5e-8f);

    float a0 = 0.f, a1 = 0.f, a2 = 0.f, a3 = 0.f;
    float a4 = 0.f, a5 = 0.f, a6 = 0.f, a7 = 0.f;

    #pragma unroll 2
    for (int s = 0; s < NSENS; s += 4) {
        // --- four independent bit-exact index chains ---
        float2 cA = sxy[s + 0];
        float2 cB = sxy[s + 1];
        float2 cC = sxy[s + 2];
        float2 cD = sxy[s + 3];

        float dxA = __fmul_rn(cA.x - fix, 1e-4f), dyA = __fmul_rn(cA.y - fiy, 1e-4f);
        float dxB = __fmul_rn(cB.x - fix, 1e-4f), dyB = __fmul_rn(cB.y - fiy, 1e-4f);
        float dxC = __fmul_rn(cC.x - fix, 1e-4f), dyC = __fmul_rn(cC.y - fiy, 1e-4f);
        float dxD = __fmul_rn(cD.x - fix, 1e-4f), dyD = __fmul_rn(cD.y - fiy, 1e-4f);

        float rA = __fadd_rn(__fmul_rn(dxA, dxA), __fmul_rn(dyA, dyA));
        float rB = __fadd_rn(__fmul_rn(dxB, dxB), __fmul_rn(dyB, dyB));
        float rC = __fadd_rn(__fmul_rn(dxC, dxC), __fmul_rn(dyC, dyC));
        float rD = __fadd_rn(__fmul_rn(dxD, dxD), __fmul_rn(dyD, dyD));

        int tA = (int)__fmul_rn(__fsqrt_rn(rA), K);
        int tB = (int)__fmul_rn(__fsqrt_rn(rB), K);
        int tC = (int)__fmul_rn(__fsqrt_rn(rC), K);
        int tD = (int)__fmul_rn(__fsqrt_rn(rD), K);

        uint4 vA = __ldg(&g_scratchH[(((unsigned)(s + 0)) << 11) + (unsigned)tA]);
        uint4 vB = __ldg(&g_scratchH[(((unsigned)(s + 1)) << 11) + (unsigned)tB]);
        uint4 vC = __ldg(&g_scratchH[(((unsigned)(s + 2)) << 11) + (unsigned)tC]);
        uint4 vD = __ldg(&g_scratchH[(((unsigned)(s + 3)) << 11) + (unsigned)tD]);

        // --- 2-level fp16 tree, then convert+accumulate in f32 ---
        __half2 q0 = __hadd2(__hadd2(h2(vA.x), h2(vB.x)), __hadd2(h2(vC.x), h2(vD.x)));
        __half2 q1 = __hadd2(__hadd2(h2(vA.y), h2(vB.y)), __hadd2(h2(vC.y), h2(vD.y)));
        __half2 q2 = __hadd2(__hadd2(h2(vA.z), h2(vB.z)), __hadd2(h2(vC.z), h2(vD.z)));
        __half2 q3 = __hadd2(__hadd2(h2(vA.w), h2(vB.w)), __hadd2(h2(vC.w), h2(vD.w)));

        float2 f01 = __half22float2(q0);
        float2 f23 = __half22float2(q1);
        float2 f45 = __half22float2(q2);
        float2 f67 = __half22float2(q3);

        a0 += f01.x; a1 += f01.y;
        a2 += f23.x; a3 += f23.y;
        a4 += f45.x; a5 += f45.y;
        a6 += f67.x; a7 += f67.y;
    }

    const int p = ix * NYg + iy;
    out[0 * NPIX + p] = a0;
    out[1 * NPIX + p] = a1;
    out[2 * NPIX + p] = a2;
    out[3 * NPIX + p] = a3;
    out[4 * NPIX + p] = a4;
    out[5 * NPIX + p] = a5;
    out[6 * NPIX + p] = a6;
    out[7 * NPIX + p] = a7;
}

// ---------------------------------------------------------------------------
// Entry point
// ---------------------------------------------------------------------------
extern "C" void kernel_launch(void* const* d_in, const int* in_sizes, int n_in,
                              void* d_out, int out_size)
{
    const float* sensor_data = (const float*)d_in[0];   // (4,2,128,2048) f32
    const int*   sensor_xy   = (const int*)d_in[1];     // (128,2) i32
    float*       out         = (float*)d_out;           // (4,2,512,512) f32

    das_transpose_kernel<<<(NSENS * (NT / 4) + 255) / 256, 256>>>(sensor_data);

    dim3 block(128);
    dim3 grid(NYg / 16, NXg / 8);
    das_main_kernel<<<grid, block>>>(sensor_xy, out);
}

// round 16
// speedup vs baseline: 2.0161x; 1.0188x over previous
#include <cuda_runtime.h>
#include <cuda_bf16.h>
#include <cuda_fp16.h>
#include <cstdint>

// Problem constants
#define NXg 512
#define NYg 512
#define NSENS 128
#define NT 2048
#define NPIX (NXg * NYg)

// fp16 scratch: [s][t] -> 8 channels x half = 16B entry. 4 MB total.
__device__ uint4 g_scratchH[NSENS * NT];

__device__ __forceinline__ unsigned pack2(float a, float b) {
    __half2 h = __floats2half2_rn(a, b);
    return *(unsigned*)&h;
}
__device__ __forceinline__ __half2 h2(unsigned u) { return *(__half2*)&u; }

// Pack two f32 into a b64 for f32x2 ops.
__device__ __forceinline__ unsigned long long packf2(float a, float b) {
    unsigned long long r;
    asm("mov.b64 %0, {%1, %2};" : "=l"(r) : "f"(a), "f"(b));
    return r;
}

// ---------------------------------------------------------------------------
// Prep kernel: transpose+quantize sensor_data [B=4][C=2][S=128][T=2048]
// -> [S][T][8ch fp16]. Each thread handles 4 consecutive t.
// ---------------------------------------------------------------------------
__global__ __launch_bounds__(256) void das_transpose_kernel(
    const float* __restrict__ sd)
{
    int idx = blockIdx.x * blockDim.x + threadIdx.x;   // 0 .. 128*512-1
    if (idx >= NSENS * (NT / 4)) return;
    int s  = idx >> 9;
    int tq = (idx & 511) << 2;

    const int bcStride = NSENS * NT;
    const float* base = sd + s * NT + tq;

    float4 c0 = *(const float4*)(base + 0 * bcStride);
    float4 c1 = *(const float4*)(base + 1 * bcStride);
    float4 c2 = *(const float4*)(base + 2 * bcStride);
    float4 c3 = *(const float4*)(base + 3 * bcStride);
    float4 c4 = *(const float4*)(base + 4 * bcStride);
    float4 c5 = *(const float4*)(base + 5 * bcStride);
    float4 c6 = *(const float4*)(base + 6 * bcStride);
    float4 c7 = *(const float4*)(base + 7 * bcStride);

    unsigned e = ((unsigned)s << 11) + (unsigned)tq;

    g_scratchH[e + 0] = make_uint4(pack2(c0.x, c1.x), pack2(c2.x, c3.x),
                                   pack2(c4.x, c5.x), pack2(c6.x, c7.x));
    g_scratchH[e + 1] = make_uint4(pack2(c0.y, c1.y), pack2(c2.y, c3.y),
                                   pack2(c4.y, c5.y), pack2(c6.y, c7.y));
    g_scratchH[e + 2] = make_uint4(pack2(c0.z, c1.z), pack2(c2.z, c3.z),
                                   pack2(c4.z, c5.z), pack2(c6.z, c7.z));
    g_scratchH[e + 3] = make_uint4(pack2(c0.w, c1.w), pack2(c2.w, c3.w),
                                   pack2(c4.w, c5.w), pack2(c6.w, c7.w));
}

// ---------------------------------------------------------------------------
// Main DAS kernel. Geometry from R10 (validated optimum).
// Index pre-sqrt math runs PACKED in f32x2 across sensor pairs — per-lane
// IEEE RN, bit-identical to the scalar chain (frozen since R3). Quad HADD2
// value tree from R15; accumulation in packed add.rn.f32x2 (R6-validated).
// ---------------------------------------------------------------------------
__global__ __launch_bounds__(128) void das_main_kernel(
    const int* __restrict__ sensor_xy,   // [128][2] int32
    float* __restrict__ out)             // [8][NPIX]
{
    // Sensor-pair layout: (cxA, cxB, cyA, cyB) per pair -> 1 LDS.128/pair.
    __shared__ float4 sxyp[NSENS / 2];

    const int tid  = threadIdx.x;        // 0..127
    const int lane = tid & 31;
    const int w    = tid >> 5;           // 0..3

    if (tid < NSENS / 2) {
        int4 q = ((const int4*)sensor_xy)[tid];   // x_{2p}, y_{2p}, x_{2p+1}, y_{2p+1}
        sxyp[tid] = make_float4((float)q.x, (float)q.z, (float)q.y, (float)q.w);
    }
    __syncthreads();

    const int ly = lane & 7;
    const int lx = lane >> 3;
    const int wy = w & 1;
    const int wx = w >> 1;

    const int iy = blockIdx.x * 16 + wy * 8 + ly;
    const int ix = blockIdx.y * 8 + wx * 4 + lx;

    const float fix = (float)ix;
    const float fiy = (float)iy;

    // XLA chain (bit-exact, validated R3): dis * fl(fl(1/VS)*fl(1/DT)).
    const float K = (1.0f / 1550.0f) * (1.0f / 2.5e-8f);

    // Packed constants for f32x2 lanes.
    const unsigned long long nfix2 = packf2(-fix, -fix);
    const unsigned long long nfiy2 = packf2(-fiy, -fiy);
    const unsigned long long e4x2  = packf2(1e-4f, 1e-4f);

    // Packed f32 accumulators.
    unsigned long long a0 = 0ull, a1 = 0ull, a2 = 0ull, a3 = 0ull;

    #pragma unroll 2
    for (int s = 0; s < NSENS; s += 4) {
        const int k = s >> 1;
        float4 m0 = sxyp[k];       // pair (s, s+1)
        float4 m1 = sxyp[k + 1];   // pair (s+2, s+3)

        unsigned long long xp0 = packf2(m0.x, m0.y);
        unsigned long long yp0 = packf2(m0.z, m0.w);
        unsigned long long xp1 = packf2(m1.x, m1.y);
        unsigned long long yp1 = packf2(m1.z, m1.w);

        // dx = (cx - fix) * 1e-4 ; dy = (cy - fiy) * 1e-4   (packed, RN/lane)
        unsigned long long dx0, dy0, dx1, dy1;
        asm("add.rn.f32x2 %0, %1, %2;" : "=l"(dx0) : "l"(xp0), "l"(nfix2));
        asm("add.rn.f32x2 %0, %1, %2;" : "=l"(dy0) : "l"(yp0), "l"(nfiy2));
        asm("add.rn.f32x2 %0, %1, %2;" : "=l"(dx1) : "l"(xp1), "l"(nfix2));
        asm("add.rn.f32x2 %0, %1, %2;" : "=l"(dy1) : "l"(yp1), "l"(nfiy2));
        asm("mul.rn.f32x2 %0, %0, %1;" : "+l"(dx0) : "l"(e4x2));
        asm("mul.rn.f32x2 %0, %0, %1;" : "+l"(dy0) : "l"(e4x2));
        asm("mul.rn.f32x2 %0, %0, %1;" : "+l"(dx1) : "l"(e4x2));
        asm("mul.rn.f32x2 %0, %0, %1;" : "+l"(dy1) : "l"(e4x2));

        // r2 = dx*dx + dy*dy (mul, mul, add — matches XLA; NO fma)
        unsigned long long sx0, sy0, sx1, sy1, r2p0, r2p1;
        asm("mul.rn.f32x2 %0, %1, %1;" : "=l"(sx0) : "l"(dx0));
        asm("mul.rn.f32x2 %0, %1, %1;" : "=l"(sy0) : "l"(dy0));
        asm("mul.rn.f32x2 %0, %1, %1;" : "=l"(sx1) : "l"(dx1));
        asm("mul.rn.f32x2 %0, %1, %1;" : "=l"(sy1) : "l"(dy1));
        asm("add.rn.f32x2 %0, %1, %2;" : "=l"(r2p0) : "l"(sx0), "l"(sy0));
        asm("add.rn.f32x2 %0, %1, %2;" : "=l"(r2p1) : "l"(sx1), "l"(sy1));

        float rA, rB, rC, rD;
        asm("mov.b64 {%0, %1}, %2;" : "=f"(rA), "=f"(rB) : "l"(r2p0));
        asm("mov.b64 {%0, %1}, %2;" : "=f"(rC), "=f"(rD) : "l"(r2p1));

        // Scalar tail: correctly-rounded sqrt, mul K, trunc (bit-exact).
        int tA = (int)__fmul_rn(__fsqrt_rn(rA), K);
        int tB = (int)__fmul_rn(__fsqrt_rn(rB), K);
        int tC = (int)__fmul_rn(__fsqrt_rn(rC), K);
        int tD = (int)__fmul_rn(__fsqrt_rn(rD), K);

        uint4 vA = __ldg(&g_scratchH[(((unsigned)(s + 0)) << 11) + (unsigned)tA]);
        uint4 vB = __ldg(&g_scratchH[(((unsigned)(s + 1)) << 11) + (unsigned)tB]);
        uint4 vC = __ldg(&g_scratchH[(((unsigned)(s + 2)) << 11) + (unsigned)tC]);
        uint4 vD = __ldg(&g_scratchH[(((unsigned)(s + 3)) << 11) + (unsigned)tD]);

        // 2-level fp16 tree (R15-validated error), convert, packed accumulate.
        __half2 q0 = __hadd2(__hadd2(h2(vA.x), h2(vB.x)), __hadd2(h2(vC.x), h2(vD.x)));
        __half2 q1 = __hadd2(__hadd2(h2(vA.y), h2(vB.y)), __hadd2(h2(vC.y), h2(vD.y)));
        __half2 q2 = __hadd2(__hadd2(h2(vA.z), h2(vB.z)), __hadd2(h2(vC.z), h2(vD.z)));
        __half2 q3 = __hadd2(__hadd2(h2(vA.w), h2(vB.w)), __hadd2(h2(vC.w), h2(vD.w)));

        float2 f01 = __half22float2(q0);
        float2 f23 = __half22float2(q1);
        float2 f45 = __half22float2(q2);
        float2 f67 = __half22float2(q3);

        unsigned long long u01 = packf2(f01.x, f01.y);
        unsigned long long u23 = packf2(f23.x, f23.y);
        unsigned long long u45 = packf2(f45.x, f45.y);
        unsigned long long u67 = packf2(f67.x, f67.y);

        asm("add.rn.f32x2 %0, %0, %1;" : "+l"(a0) : "l"(u01));
        asm("add.rn.f32x2 %0, %0, %1;" : "+l"(a1) : "l"(u23));
        asm("add.rn.f32x2 %0, %0, %1;" : "+l"(a2) : "l"(u45));
        asm("add.rn.f32x2 %0, %0, %1;" : "+l"(a3) : "l"(u67));
    }

    const int p = ix * NYg + iy;
    unsigned lo, hi;
    asm("mov.b64 {%0,%1}, %2;" : "=r"(lo), "=r"(hi) : "l"(a0));
    out[0 * NPIX + p] = __uint_as_float(lo);
    out[1 * NPIX + p] = __uint_as_float(hi);
    asm("mov.b64 {%0,%1}, %2;" : "=r"(lo), "=r"(hi) : "l"(a1));
    out[2 * NPIX + p] = __uint_as_float(lo);
    out[3 * NPIX + p] = __uint_as_float(hi);
    asm("mov.b64 {%0,%1}, %2;" : "=r"(lo), "=r"(hi) : "l"(a2));
    out[4 * NPIX + p] = __uint_as_float(lo);
    out[5 * NPIX + p] = __uint_as_float(hi);
    asm("mov.b64 {%0,%1}, %2;" : "=r"(lo), "=r"(hi) : "l"(a3));
    out[6 * NPIX + p] = __uint_as_float(lo);
    out[7 * NPIX + p] = __uint_as_float(hi);
}

// ---------------------------------------------------------------------------
// Entry point
// ---------------------------------------------------------------------------
extern "C" void kernel_launch(void* const* d_in, const int* in_sizes, int n_in,
                              void* d_out, int out_size)
{
    const float* sensor_data = (const float*)d_in[0];   // (4,2,128,2048) f32
    const int*   sensor_xy   = (const int*)d_in[1];     // (128,2) i32
    float*       out         = (float*)d_out;           // (4,2,512,512) f32

    das_transpose_kernel<<<(NSENS * (NT / 4) + 255) / 256, 256>>>(sensor_data);

    dim3 block(128);
    dim3 grid(NYg / 16, NXg / 8);
    das_main_kernel<<<grid, block>>>(sensor_xy, out);
}